// round 8
// baseline (speedup 1.0000x reference)
#include <cuda_runtime.h>
#include <cuda_bf16.h>
#include <math.h>
#include <stdint.h>

#define DM   128
#define NH   8
#define HD   16
#define KTOT 164          // 9 + 25 + 49 + 81
#define PER_B 21504       // 128*128 + 64*64 + 32*32
#define MAXN 2048
#define MAXROWS (2*PER_B + MAXN*9)
#define MAXL 4

typedef unsigned long long ull;

// ---------------- device scratch ----------------
__device__ float g_x  [MAXN*DM];
__device__ float g_h  [MAXN*DM];
__device__ float g_q  [MAXN*DM];
__device__ float g_o  [MAXN*DM];
__device__ float g_t  [MAXN*512];
__device__ float g_qcs[MAXN*16];
__device__ float g_kcs[(size_t)MAXN*KTOT*16];
__device__ int   g_kidx[MAXN*KTOT];
__device__ int   g_kval[MAXN*KTOT];
__device__ int   g_rowsrc[MAXROWS];
__device__ float g_Kc[(size_t)MAXROWS*DM];
__device__ float g_Vc[(size_t)MAXROWS*DM];
__device__ __nv_bfloat16 g_WBhi[MAXL*256*128];   // [layer][n: Wk|Wv][k]
__device__ __nv_bfloat16 g_WBlo[MAXL*256*128];
__device__ float g_ktab[4*2*264*8];              // [level][axis][g+4][4cos,4sin]

__device__ __constant__ float c_invfreq[4] = {1.0f, 0.56234132519f, 0.316227766017f, 0.177827941004f};

// ---------------- helpers ----------------
__device__ __forceinline__ ull fma2(ull a, ull b, ull c) {
    ull d; asm("fma.rn.f32x2 %0, %1, %2, %3;" : "=l"(d) : "l"(a), "l"(b), "l"(c)); return d;
}
__device__ __forceinline__ ull pack2(float f) {
    ull r; asm("mov.b64 %0, {%1, %1};" : "=l"(r) : "r"(__float_as_uint(f))); return r;
}
__device__ __forceinline__ ull packab(float a, float b) {
    ull r; asm("mov.b64 %0, {%1, %2};" : "=l"(r) : "r"(__float_as_uint(a)), "r"(__float_as_uint(b))); return r;
}
__device__ __forceinline__ void unpack2(ull v, float& lo, float& hi) {
    unsigned int a, b; asm("mov.b64 {%0, %1}, %2;" : "=r"(a), "=r"(b) : "l"(v));
    lo = __uint_as_float(a); hi = __uint_as_float(b);
}
__device__ __forceinline__ float gelu_tanh(float v) {
    float u = 0.7978845608028654f * (v + 0.044715f * v * v * v);
    return 0.5f * v * (1.f + tanhf(u));
}
__device__ __forceinline__ int batch_of(int q, const int* qbo, int n_off) {
    int b = 0;
    for (int t = 1; t < n_off - 1; t++) if (q >= qbo[t]) b = t;
    return b;
}
__device__ __forceinline__ uint32_t smem_u32(const void* p) {
    uint32_t a;
    asm("{ .reg .u64 t; cvta.to.shared.u64 t, %1; cvt.u32.u64 %0, t; }" : "=r"(a) : "l"(p));
    return a;
}
__device__ __forceinline__ uint32_t bf2(float a, float b) {
    __nv_bfloat162 h = __floats2bfloat162_rn(a, b);
    return *(uint32_t*)&h;
}
__device__ __forceinline__ float bflo(float x, __nv_bfloat16 hi) {
    return x - __bfloat162float(hi);
}
__device__ __forceinline__ void ldsm_x4(uint32_t addr, uint32_t& r0, uint32_t& r1, uint32_t& r2, uint32_t& r3) {
    asm volatile("ldmatrix.sync.aligned.m8n8.x4.shared.b16 {%0,%1,%2,%3}, [%4];"
                 : "=r"(r0), "=r"(r1), "=r"(r2), "=r"(r3) : "r"(addr));
}
__device__ __forceinline__ void mma_bf16(float* c, uint32_t a0, uint32_t a1, uint32_t a2, uint32_t a3,
                                         uint32_t b0, uint32_t b1) {
    asm volatile("mma.sync.aligned.m16n8k16.row.col.f32.bf16.bf16.f32 "
                 "{%0,%1,%2,%3}, {%4,%5,%6,%7}, {%8,%9}, {%0,%1,%2,%3};"
                 : "+f"(c[0]), "+f"(c[1]), "+f"(c[2]), "+f"(c[3])
                 : "r"(a0), "r"(a1), "r"(a2), "r"(a3), "r"(b0), "r"(b1));
}

// ---------------- precompute ----------------
__global__ void copy_x_kernel(const float* __restrict__ src, int n) {
    int i = blockIdx.x * blockDim.x + threadIdx.x;
    if (i < n) g_x[i] = src[i];
}

__global__ void build_wt_kernel(const float* __restrict__ Wk, const float* __restrict__ Wv, int nl) {
    int id = blockIdx.x * blockDim.x + threadIdx.x;
    if (id >= nl * 256 * 128) return;
    int li = id / (256 * 128);
    int r  = id % (256 * 128);
    int n = r / 128, k = r % 128;
    float w = (n < 128) ? Wk[li*DM*DM + k*DM + n] : Wv[li*DM*DM + k*DM + (n - 128)];
    __nv_bfloat16 hi = __float2bfloat16(w);
    g_WBhi[id] = hi;
    g_WBlo[id] = __float2bfloat16(w - __bfloat162float(hi));
}

// cos/sin tables per (level, axis, integer coord)
__global__ void build_ktab_kernel(const int* __restrict__ shapes) {
    int id = blockIdx.x * blockDim.x + threadIdx.x;
    if (id >= 4 * 2 * 264) return;
    int l = id / (2 * 264);
    int axis = (id / 264) & 1;
    int gidx = id % 264;
    int g = gidx - 4;
    float scale = (float)shapes[2*l + axis] / (float)shapes[axis];
    float kp = ((float)g + 0.5f) / scale;
    float* t = &g_ktab[(size_t)id * 8];
    #pragma unroll
    for (int f = 0; f < 4; f++) {
        float a = kp * c_invfreq[f];
        t[f] = cosf(a);
        t[4 + f] = sinf(a);
    }
}

__global__ void build_rowsrc_kernel(const float* __restrict__ qpos,
                                    const int* __restrict__ qbo, int n_off,
                                    int R123, int R) {
    int e = blockIdx.x * blockDim.x + threadIdx.x;
    if (e >= R) return;
    int src;
    if (e < R123) {
        int b = e / PER_B, r = e % PER_B;
        int l, i, j;
        if (r < 16384)      { l = 1; i = r >> 7; j = r & 127; }
        else if (r < 20480) { int rr = r - 16384; l = 2; i = rr >> 6; j = rr & 63; }
        else                { int rr = r - 20480; l = 3; i = rr >> 5; j = rr & 31; }
        src = ((b * 256 + i) * 256 + j) * 4 + l;
    } else {
        int e2 = e - R123;
        int q = e2 / 9, t = e2 % 9;
        int b = batch_of(q, qbo, n_off);
        float p0 = qpos[2*q], p1 = qpos[2*q+1];
        int c0 = (int)floorf(p0), c1 = (int)floorf(p1);
        int gi = c0 + t / 3 - 1, gj = c1 + t % 3 - 1;
        gi = min(max(gi, 0), 255); gj = min(max(gj, 0), 255);
        src = ((b * 256 + gi) * 256 + gj) * 4 + 0;
    }
    g_rowsrc[e] = src;
}

__global__ void build_keys_kernel(const float* __restrict__ qpos,
                                  const int* __restrict__ qbo, int n_off,
                                  const int* __restrict__ shapes,
                                  int N, int R123) {
    int id = blockIdx.x * blockDim.x + threadIdx.x;
    if (id >= N * KTOT) return;
    int q = id / KTOT, k = id % KTOT;
    int l, t, d;
    if      (k < 9)  { l = 0; t = k;      d = 3; }
    else if (k < 34) { l = 1; t = k - 9;  d = 5; }
    else if (k < 83) { l = 2; t = k - 34; d = 7; }
    else             { l = 3; t = k - 83; d = 9; }
    int Hl = shapes[2*l], Wl = shapes[2*l+1];
    float sh = (float)Hl / (float)shapes[0];
    float sw = (float)Wl / (float)shapes[1];
    float p0 = qpos[2*q], p1 = qpos[2*q+1];
    int c0 = (int)floorf(p0 * sh), c1 = (int)floorf(p1 * sw);
    int gi = c0 + t / d - d / 2;
    int gj = c1 + t % d - d / 2;
    int valid = (gi >= 0 && gi < Hl && gj >= 0 && gj < Wl);
    int ci = min(max(gi, 0), Hl - 1), cj = min(max(gj, 0), Wl - 1);
    int b = batch_of(q, qbo, n_off);
    int idx;
    if (l == 0) idx = R123 + q * 9 + t;
    else {
        int base = (l == 1) ? 0 : (l == 2) ? 16384 : 20480;
        idx = b * PER_B + base + ci * Wl + cj;
    }
    g_kidx[id] = idx;
    g_kval[id] = valid;
    const float* ti = &g_ktab[(size_t)((l * 2 + 0) * 264 + (gi + 4)) * 8];
    const float* tj = &g_ktab[(size_t)((l * 2 + 1) * 264 + (gj + 4)) * 8];
    float* cs = &g_kcs[(size_t)id * 16];
    #pragma unroll
    for (int f = 0; f < 4; f++) {
        cs[f]      = ti[f];      cs[8  + f] = ti[4 + f];
        cs[4 + f]  = tj[f];      cs[12 + f] = tj[4 + f];
    }
}

__global__ void build_qcs_kernel(const float* __restrict__ qpos, int N) {
    int q = blockIdx.x * blockDim.x + threadIdx.x;
    if (q >= N) return;
    float p0 = qpos[2*q], p1 = qpos[2*q+1];
    float* cs = &g_qcs[q * 16];
    #pragma unroll
    for (int f = 0; f < 4; f++) {
        float a0 = p0 * c_invfreq[f];
        float a1 = p1 * c_invfreq[f];
        cs[f]      = cosf(a0);  cs[8  + f] = sinf(a0);
        cs[4 + f]  = cosf(a1);  cs[12 + f] = sinf(a1);
    }
}

// ---------------- mma.sync KV projection ----------------
#define A_STR 136
#define B_STR 40
#define OFF_AHI 0
#define OFF_ALO 34816
#define OFF_BHI 69632
#define OFF_BLO 79872
#define SM_MMA_TOTAL 90112

__global__ void __launch_bounds__(256, 2)
kvproj_mma_kernel(const float* __restrict__ fm, int li, int R) {
    extern __shared__ char smem[];
    uint32_t sbase = smem_u32(smem);
    int tid = threadIdx.x;
    int wid = tid >> 5, lane = tid & 31;
    int wm = wid & 3, wn = wid >> 2;        // warp tile: rows wm*32, cols wn*64
    int row0 = blockIdx.x * 128;

    // ---- phase 1: gather + convert A (128 rows x 128 k) to bf16 hi/lo smem ----
    #pragma unroll
    for (int it = 0; it < 16; it++) {
        int idx = tid + 256 * it;            // 0..4095 float4s
        int r = idx >> 5, c4 = idx & 31;
        int row = row0 + r; if (row >= R) row = R - 1;
        int src = g_rowsrc[row];
        float4 v = *(const float4*)(fm + (size_t)src * 128 + c4 * 4);
        __nv_bfloat16 hx = __float2bfloat16(v.x);
        __nv_bfloat16 hy = __float2bfloat16(v.y);
        __nv_bfloat16 hz = __float2bfloat16(v.z);
        __nv_bfloat16 hw = __float2bfloat16(v.w);
        uint32_t h01 = ((uint32_t)*(uint16_t*)&hy << 16) | *(uint16_t*)&hx;
        uint32_t h23 = ((uint32_t)*(uint16_t*)&hw << 16) | *(uint16_t*)&hz;
        uint32_t l01 = bf2(bflo(v.x, hx), bflo(v.y, hy));
        uint32_t l23 = bf2(bflo(v.z, hz), bflo(v.w, hw));
        uint32_t off = (uint32_t)(r * A_STR + c4 * 4) * 2;
        *(uint2*)(smem + OFF_AHI + off) = make_uint2(h01, h23);
        *(uint2*)(smem + OFF_ALO + off) = make_uint2(l01, l23);
    }

    const __nv_bfloat16* wbh = g_WBhi + (size_t)li * 256 * 128;
    const __nv_bfloat16* wbl = g_WBlo + (size_t)li * 256 * 128;

    for (int h = 0; h < 2; h++) {
        float acc[2][8][4];
        #pragma unroll
        for (int i = 0; i < 2; i++)
            #pragma unroll
            for (int j = 0; j < 8; j++)
                #pragma unroll
                for (int e = 0; e < 4; e++) acc[i][j][e] = 0.f;

        for (int c = 0; c < 4; c++) {
            __syncthreads();
            #pragma unroll
            for (int it = 0; it < 2; it++) {
                int idx = tid + 256 * it;            // 0..511
                int n = idx >> 2, kk = (idx & 3) * 8;
                const __nv_bfloat16* sh = wbh + ((size_t)(h * 128 + n)) * 128 + c * 32 + kk;
                const __nv_bfloat16* sl = wbl + ((size_t)(h * 128 + n)) * 128 + c * 32 + kk;
                uint32_t off = (uint32_t)(n * B_STR + kk) * 2;
                *(uint4*)(smem + OFF_BHI + off) = *(const uint4*)sh;
                *(uint4*)(smem + OFF_BLO + off) = *(const uint4*)sl;
            }
            __syncthreads();

            #pragma unroll
            for (int s = 0; s < 2; s++) {
                uint32_t ah[2][4], al[2][4];
                #pragma unroll
                for (int i = 0; i < 2; i++) {
                    uint32_t arow = wm * 32 + i * 16 + (lane & 15);
                    uint32_t akol = c * 32 + s * 16 + ((lane >> 4) << 3);
                    uint32_t aoff = (arow * A_STR + akol) * 2;
                    ldsm_x4(sbase + OFF_AHI + aoff, ah[i][0], ah[i][1], ah[i][2], ah[i][3]);
                    ldsm_x4(sbase + OFF_ALO + aoff, al[i][0], al[i][1], al[i][2], al[i][3]);
                }
                #pragma unroll
                for (int jj = 0; jj < 4; jj++) {
                    int m = lane >> 3, w8 = lane & 7;
                    uint32_t bn = wn * 64 + (2 * jj + (m >> 1)) * 8 + w8;
                    uint32_t bk = s * 16 + (m & 1) * 8;
                    uint32_t boff = (bn * B_STR + bk) * 2;
                    uint32_t bh0, bh1, bh2, bh3, bl0, bl1, bl2, bl3;
                    ldsm_x4(sbase + OFF_BHI + boff, bh0, bh1, bh2, bh3);
                    ldsm_x4(sbase + OFF_BLO + boff, bl0, bl1, bl2, bl3);
                    #pragma unroll
                    for (int i = 0; i < 2; i++) {
                        mma_bf16(acc[i][2*jj],   ah[i][0], ah[i][1], ah[i][2], ah[i][3], bh0, bh1);
                        mma_bf16(acc[i][2*jj],   ah[i][0], ah[i][1], ah[i][2], ah[i][3], bl0, bl1);
                        mma_bf16(acc[i][2*jj],   al[i][0], al[i][1], al[i][2], al[i][3], bh0, bh1);
                        mma_bf16(acc[i][2*jj+1], ah[i][0], ah[i][1], ah[i][2], ah[i][3], bh2, bh3);
                        mma_bf16(acc[i][2*jj+1], ah[i][0], ah[i][1], ah[i][2], ah[i][3], bl2, bl3);
                        mma_bf16(acc[i][2*jj+1], al[i][0], al[i][1], al[i][2], al[i][3], bh2, bh3);
                    }
                }
            }
        }
        float* dstbase = h ? g_Vc : g_Kc;
        #pragma unroll
        for (int i = 0; i < 2; i++) {
            int rA = row0 + wm * 32 + i * 16 + (lane >> 2);
            int rB = rA + 8;
            #pragma unroll
            for (int j = 0; j < 8; j++) {
                int col = wn * 64 + j * 8 + (lane & 3) * 2;
                if (rA < R) *(float2*)(dstbase + (size_t)rA * 128 + col) = make_float2(acc[i][j][0], acc[i][j][1]);
                if (rB < R) *(float2*)(dstbase + (size_t)rB * 128 + col) = make_float2(acc[i][j][2], acc[i][j][3]);
            }
        }
    }
}

// ---------------- per-layer kernels ----------------
// LN1 + Qproj + RoPE, 8 queries per block, 128 threads; W re-read cut 8x.
__global__ void ln_qproj_kernel(const float* __restrict__ lg, const float* __restrict__ lb,
                                const float* __restrict__ Wq, int N) {
    int q0 = blockIdx.x * 8, tid = threadIdx.x;
    int lane = tid & 31, w = tid >> 5;
    __shared__ float sh2[8][128];
    __shared__ float red1[8][4], red2[8][4];
    float xv[8];
    #pragma unroll
    for (int r = 0; r < 8; r++) {
        int q = q0 + r;
        xv[r] = (q < N) ? g_x[q*DM + tid] : 0.f;
    }
    #pragma unroll
    for (int r = 0; r < 8; r++) {
        float s1 = xv[r], s2 = xv[r] * xv[r];
        #pragma unroll
        for (int o = 16; o; o >>= 1) {
            s1 += __shfl_xor_sync(0xffffffffu, s1, o);
            s2 += __shfl_xor_sync(0xffffffffu, s2, o);
        }
        if (lane == 0) { red1[r][w] = s1; red2[r][w] = s2; }
    }
    __syncthreads();
    float lgv = lg[tid], lbv = lb[tid];
    #pragma unroll
    for (int r = 0; r < 8; r++) {
        float s1 = red1[r][0] + red1[r][1] + red1[r][2] + red1[r][3];
        float s2 = red2[r][0] + red2[r][1] + red2[r][2] + red2[r][3];
        float mean = s1 * (1.f / 128.f);
        float var  = s2 * (1.f / 128.f) - mean * mean;
        sh2[r][tid] = (xv[r] - mean) * rsqrtf(var + 1e-5f) * lgv + lbv;
    }
    __syncthreads();
    float acc[8];
    #pragma unroll
    for (int r = 0; r < 8; r++) acc[r] = 0.f;
    #pragma unroll 8
    for (int i = 0; i < 128; i++) {
        float wv = Wq[i * DM + tid];
        #pragma unroll
        for (int r = 0; r < 8; r++) acc[r] += sh2[r][i] * wv;
    }
    int p = (tid >> 1) & 7;
    #pragma unroll
    for (int r = 0; r < 8; r++) {
        int q = q0 + r;
        float part = __shfl_xor_sync(0xffffffffu, acc[r], 1);
        float x1 = (tid & 1) ? part : acc[r];
        float x2 = (tid & 1) ? acc[r] : part;
        if (q < N) {
            float cc = g_qcs[q*16 + p], ss = g_qcs[q*16 + 8 + p];
            g_q[q*DM + tid] = (tid & 1) ? (x1 * ss + x2 * cc) : (x1 * cc - x2 * ss);
        }
    }
}

__global__ void attn_kernel() {
    int q = blockIdx.x, tid = threadIdx.x;
    int lane = tid & 31, w = tid >> 5;
    __shared__ float sq[128];
    __shared__ float ssc[8 * KTOT];
    __shared__ int   skidx[KTOT];
    sq[tid] = g_q[q*DM + tid];
    for (int k = tid; k < KTOT; k += 128) skidx[k] = g_kidx[q*KTOT + k];
    __syncthreads();
    float4 qv = *(const float4*)&sq[lane * 4];
    for (int k = w; k < KTOT; k += 4) {
        int idx = skidx[k];
        float4 kv = *(const float4*)&g_Kc[(size_t)idx*DM + lane*4];
        const float* cs = &g_kcs[(size_t)((size_t)q*KTOT + k) * 16];
        float csv = (lane < 16) ? cs[lane] : 0.f;
        int m = lane & 3;
        float c0 = __shfl_sync(0xffffffffu, csv, 2*m);
        float s0 = __shfl_sync(0xffffffffu, csv, 8 + 2*m);
        float c1 = __shfl_sync(0xffffffffu, csv, 2*m + 1);
        float s1 = __shfl_sync(0xffffffffu, csv, 9 + 2*m);
        float r0 = kv.x*c0 - kv.y*s0;
        float r1 = kv.x*s0 + kv.y*c0;
        float r2 = kv.z*c1 - kv.w*s1;
        float r3 = kv.z*s1 + kv.w*c1;
        float ps = r0*qv.x + r1*qv.y + r2*qv.z + r3*qv.w;
        ps += __shfl_xor_sync(0xffffffffu, ps, 1);
        ps += __shfl_xor_sync(0xffffffffu, ps, 2);
        if ((lane & 3) == 0) {
            int h = lane >> 2;
            int val = g_kval[q*KTOT + k];
            ssc[h*KTOT + k] = val ? ps * 0.25f : -1.0e9f;
        }
    }
    __syncthreads();
    #pragma unroll
    for (int hh = 0; hh < 2; hh++) {
        int h = w * 2 + hh;
        float mx = -3.0e38f;
        for (int k = lane; k < KTOT; k += 32) mx = fmaxf(mx, ssc[h*KTOT + k]);
        #pragma unroll
        for (int o = 16; o; o >>= 1) mx = fmaxf(mx, __shfl_xor_sync(0xffffffffu, mx, o));
        float sum = 0.f;
        for (int k = lane; k < KTOT; k += 32) {
            float e = expf(ssc[h*KTOT + k] - mx);
            ssc[h*KTOT + k] = e;
            sum += e;
        }
        #pragma unroll
        for (int o = 16; o; o >>= 1) sum += __shfl_xor_sync(0xffffffffu, sum, o);
        float inv = 1.f / sum;
        for (int k = lane; k < KTOT; k += 32) ssc[h*KTOT + k] *= inv;
    }
    __syncthreads();
    int h = tid >> 4;
    float acc = 0.f;
    #pragma unroll 4
    for (int k = 0; k < KTOT; k++)
        acc += ssc[h*KTOT + k] * g_Vc[(size_t)skidx[k]*DM + tid];
    g_o[q*DM + tid] = acc;
}

// x += o @ Wo ; h = LN2(x).  8 queries per block.
__global__ void oproj_ln2_kernel(const float* __restrict__ Wo,
                                 const float* __restrict__ lg, const float* __restrict__ lb, int N) {
    int q0 = blockIdx.x * 8, tid = threadIdx.x;
    int lane = tid & 31, w = tid >> 5;
    __shared__ float sh2[8][128];
    __shared__ float red1[8][4], red2[8][4];
    #pragma unroll
    for (int r = 0; r < 8; r++) {
        int q = q0 + r;
        sh2[r][tid] = (q < N) ? g_o[q*DM + tid] : 0.f;
    }
    __syncthreads();
    float acc[8];
    #pragma unroll
    for (int r = 0; r < 8; r++) acc[r] = 0.f;
    #pragma unroll 8
    for (int i = 0; i < 128; i++) {
        float wv = Wo[i * DM + tid];
        #pragma unroll
        for (int r = 0; r < 8; r++) acc[r] += sh2[r][i] * wv;
    }
    float xv[8];
    #pragma unroll
    for (int r = 0; r < 8; r++) {
        int q = q0 + r;
        xv[r] = acc[r] + ((q < N) ? g_x[q*DM + tid] : 0.f);
        if (q < N) g_x[q*DM + tid] = xv[r];
    }
    #pragma unroll
    for (int r = 0; r < 8; r++) {
        float s1 = xv[r], s2 = xv[r] * xv[r];
        #pragma unroll
        for (int o = 16; o; o >>= 1) {
            s1 += __shfl_xor_sync(0xffffffffu, s1, o);
            s2 += __shfl_xor_sync(0xffffffffu, s2, o);
        }
        if (lane == 0) { red1[r][w] = s1; red2[r][w] = s2; }
    }
    __syncthreads();
    float lgv = lg[tid], lbv = lb[tid];
    #pragma unroll
    for (int r = 0; r < 8; r++) {
        int q = q0 + r;
        if (q >= N) continue;
        float s1 = red1[r][0] + red1[r][1] + red1[r][2] + red1[r][3];
        float s2 = red2[r][0] + red2[r][1] + red2[r][2] + red2[r][3];
        float mean = s1 * (1.f / 128.f);
        float var  = s2 * (1.f / 128.f) - mean * mean;
        g_h[q*DM + tid] = (xv[r] - mean) * rsqrtf(var + 1e-5f) * lgv + lbv;
    }
}

// t = gelu(h @ W1 + b1), 16 queries per block, 256 threads.
__global__ void ffn1_kernel(const float* __restrict__ W1, const float* __restrict__ pb, int N) {
    int q0 = blockIdx.x * 16, tid = threadIdx.x;
    __shared__ float sh2[16][128];
    for (int i = tid; i < 2048; i += 256) {
        int r = i >> 7, c = i & 127;
        int q = q0 + r;
        sh2[r][c] = (q < N) ? g_h[q*DM + c] : 0.f;
    }
    __syncthreads();
    ull acc0[8], acc1[8];
    #pragma unroll
    for (int p = 0; p < 8; p++) { acc0[p] = 0ull; acc1[p] = 0ull; }
    #pragma unroll 4
    for (int i = 0; i < 128; i++) {
        ull w0 = pack2(W1[i*512 + tid]);
        ull w1 = pack2(W1[i*512 + 256 + tid]);
        #pragma unroll
        for (int p = 0; p < 8; p++) {
            ull hp = packab(sh2[2*p][i], sh2[2*p+1][i]);
            acc0[p] = fma2(hp, w0, acc0[p]);
            acc1[p] = fma2(hp, w1, acc1[p]);
        }
    }
    float bb0 = pb[tid], bb1 = pb[256 + tid];
    #pragma unroll
    for (int p = 0; p < 8; p++) {
        float a0, a1, b0v, b1v;
        unpack2(acc0[p], a0, a1);
        unpack2(acc1[p], b0v, b1v);
        int qA = q0 + 2*p, qB = q0 + 2*p + 1;
        if (qA < N) { g_t[qA*512 + tid] = gelu_tanh(a0 + bb0); g_t[qA*512 + 256 + tid] = gelu_tanh(b0v + bb1); }
        if (qB < N) { g_t[qB*512 + tid] = gelu_tanh(a1 + bb0); g_t[qB*512 + 256 + tid] = gelu_tanh(b1v + bb1); }
    }
}

// x += t @ W2 + b2, 16 queries per block, 128 threads.
__global__ void ffn2_kernel(const float* __restrict__ W2, const float* __restrict__ pb, int N) {
    int q0 = blockIdx.x * 16, tid = threadIdx.x;
    __shared__ float st[16][512];
    for (int i = tid; i < 8192; i += 128) {
        int r = i >> 9, c = i & 511;
        int q = q0 + r;
        st[r][c] = (q < N) ? g_t[q*512 + c] : 0.f;
    }
    __syncthreads();
    ull acc[8];
    #pragma unroll
    for (int p = 0; p < 8; p++) acc[p] = 0ull;
    #pragma unroll 4
    for (int i = 0; i < 512; i++) {
        ull wv = pack2(W2[i*128 + tid]);
        #pragma unroll
        for (int p = 0; p < 8; p++) {
            ull tp = packab(st[2*p][i], st[2*p+1][i]);
            acc[p] = fma2(tp, wv, acc[p]);
        }
    }
    float bb = pb[tid];
    #pragma unroll
    for (int p = 0; p < 8; p++) {
        float a0, a1;
        unpack2(acc[p], a0, a1);
        int qA = q0 + 2*p, qB = q0 + 2*p + 1;
        if (qA < N) g_x[qA*DM + tid] += a0 + bb;
        if (qB < N) g_x[qB*DM + tid] += a1 + bb;
    }
}

__global__ void logits_kernel(const float* __restrict__ fm, const float* __restrict__ qpos,
                              const int* __restrict__ qbo, int n_off,
                              const int* __restrict__ shapes, float* __restrict__ out) {
    int q = blockIdx.x, tid = threadIdx.x;
    int lane = tid & 31, w = tid >> 5;
    __shared__ float sx[128];
    __shared__ int sb;
    if (tid < 128) sx[tid] = g_x[q*DM + tid];
    if (tid == 0) sb = batch_of(q, qbo, n_off);
    __syncthreads();
    int H0 = shapes[0], W0 = shapes[1];
    float p0 = qpos[2*q], p1 = qpos[2*q+1];
    int c0 = (int)floorf(p0), c1 = (int)floorf(p1);
    float4 xv = *(const float4*)&sx[lane * 4];
    int b = sb;
    for (int pp = w; pp < 49; pp += 8) {
        int gi = c0 + pp / 7 - 3;
        int gj = c1 + pp % 7 - 3;
        bool valid = (gi >= 0 && gi < H0 && gj >= 0 && gj < W0);
        int ci = min(max(gi, 0), H0 - 1), cj = min(max(gj, 0), W0 - 1);
        const float* f = fm + ((((size_t)b * 256 + ci) * 256 + cj) * 4 + 0) * 128;
        float4 fv = *(const float4*)(f + lane * 4);
        float d = fv.x*xv.x + fv.y*xv.y + fv.z*xv.z + fv.w*xv.w;
        #pragma unroll
        for (int o = 16; o; o >>= 1) d += __shfl_xor_sync(0xffffffffu, d, o);
        if (lane == 0) out[q*49 + pp] = valid ? d : 0.f;
    }
}

// ---------------- launch ----------------
extern "C" void kernel_launch(void* const* d_in, const int* in_sizes, int n_in,
                              void* d_out, int out_size) {
    const float* queries = (const float*)d_in[0];
    const int*   qbo     = (const int*)  d_in[1];
    const float* qpos    = (const float*)d_in[2];
    const float* fm      = (const float*)d_in[3];
    const int*   shapes  = (const int*)  d_in[4];
    const float* Wq      = (const float*)d_in[5];
    const float* Wk      = (const float*)d_in[6];
    const float* Wv      = (const float*)d_in[7];
    const float* Wo      = (const float*)d_in[8];
    const float* ln1g    = (const float*)d_in[9];
    const float* ln1b    = (const float*)d_in[10];
    const float* ln2g    = (const float*)d_in[11];
    const float* ln2b    = (const float*)d_in[12];
    const float* W1      = (const float*)d_in[13];
    const float* b1      = (const float*)d_in[14];
    const float* W2      = (const float*)d_in[15];
    const float* b2      = (const float*)d_in[16];

    int N     = in_sizes[0] / DM;
    int n_off = in_sizes[1];
    int nl    = in_sizes[5] / (DM * DM);
    int B     = in_sizes[3] / (256 * 256 * 4 * DM);
    int R123  = B * PER_B;
    int R     = R123 + N * 9;
    int gridR = (R + 127) / 128;

    cudaFuncSetAttribute(kvproj_mma_kernel, cudaFuncAttributeMaxDynamicSharedMemorySize, SM_MMA_TOTAL);

    // ordering: kvproj at launch index 3 so the ncu window catches it
    build_rowsrc_kernel<<<(R + 255) / 256, 256>>>(qpos, qbo, n_off, R123, R);
    build_wt_kernel<<<(nl*256*128 + 255) / 256, 256>>>(Wk, Wv, nl);
    build_ktab_kernel<<<(4*2*264 + 127) / 128, 128>>>(shapes);
    kvproj_mma_kernel<<<gridR, 256, SM_MMA_TOTAL>>>(fm, 0, R);
    build_qcs_kernel<<<(N + 127) / 128, 128>>>(qpos, N);
    copy_x_kernel<<<(N*DM + 255) / 256, 256>>>(queries, N * DM);
    build_keys_kernel<<<(N*KTOT + 127) / 128, 128>>>(qpos, qbo, n_off, shapes, N, R123);

    for (int li = 0; li < nl; li++) {
        if (li > 0)
            kvproj_mma_kernel<<<gridR, 256, SM_MMA_TOTAL>>>(fm, li, R);
        ln_qproj_kernel<<<(N + 7) / 8, 128>>>(ln1g + li*DM, ln1b + li*DM, Wq + li*DM*DM, N);
        attn_kernel<<<N, 128>>>();
        oproj_ln2_kernel<<<(N + 7) / 8, 128>>>(Wo + li*DM*DM, ln2g + li*DM, ln2b + li*DM, N);
        ffn1_kernel<<<(N + 15) / 16, 256>>>(W1 + li*DM*512, b1 + li*512, N);
        ffn2_kernel<<<(N + 15) / 16, 128>>>(W2 + li*512*DM, b2 + li*DM, N);
    }
    logits_kernel<<<N, 256>>>(fm, qpos, qbo, n_off, shapes, (float*)d_out);
}

// round 9
// speedup vs baseline: 1.0825x; 1.0825x over previous
#include <cuda_runtime.h>
#include <cuda_bf16.h>
#include <math.h>
#include <stdint.h>

#define DM   128
#define NH   8
#define HD   16
#define KTOT 164          // 9 + 25 + 49 + 81
#define PER_B 21504       // 128*128 + 64*64 + 32*32
#define MAXN 2048
#define MAXROWS (2*PER_B + MAXN*9)
#define MAXL 4

typedef unsigned long long ull;

// ---------------- device scratch ----------------
__device__ float g_x  [MAXN*DM];
__device__ float g_h  [MAXN*DM];
__device__ float g_q  [MAXN*DM];
__device__ float g_o  [MAXN*DM];
__device__ float g_t  [MAXN*512];
__device__ float g_qcs[MAXN*16];
__device__ float g_kcs[(size_t)MAXN*KTOT*16];
__device__ int   g_kidx[MAXN*KTOT];
__device__ int   g_kval[MAXN*KTOT];
__device__ int   g_rowsrc[MAXROWS];
__device__ float g_Kc[(size_t)MAXROWS*DM];
__device__ float g_Vc[(size_t)MAXROWS*DM];
__device__ __nv_bfloat16 g_WBhi[MAXL*256*128];   // [layer][n: Wk|Wv][k]
__device__ __nv_bfloat16 g_WBlo[MAXL*256*128];
__device__ float g_ktab[4*2*264*8];              // [level][axis][g+4][4cos,4sin]

__device__ __constant__ float c_invfreq[4] = {1.0f, 0.56234132519f, 0.316227766017f, 0.177827941004f};

// ---------------- helpers ----------------
__device__ __forceinline__ ull fma2(ull a, ull b, ull c) {
    ull d; asm("fma.rn.f32x2 %0, %1, %2, %3;" : "=l"(d) : "l"(a), "l"(b), "l"(c)); return d;
}
__device__ __forceinline__ ull pack2(float f) {
    ull r; asm("mov.b64 %0, {%1, %1};" : "=l"(r) : "r"(__float_as_uint(f))); return r;
}
__device__ __forceinline__ ull packab(float a, float b) {
    ull r; asm("mov.b64 %0, {%1, %2};" : "=l"(r) : "r"(__float_as_uint(a)), "r"(__float_as_uint(b))); return r;
}
__device__ __forceinline__ void unpack2(ull v, float& lo, float& hi) {
    unsigned int a, b; asm("mov.b64 {%0, %1}, %2;" : "=r"(a), "=r"(b) : "l"(v));
    lo = __uint_as_float(a); hi = __uint_as_float(b);
}
__device__ __forceinline__ float gelu_tanh(float v) {
    float u = 0.7978845608028654f * (v + 0.044715f * v * v * v);
    return 0.5f * v * (1.f + tanhf(u));
}
__device__ __forceinline__ int batch_of(int q, const int* qbo, int n_off) {
    int b = 0;
    for (int t = 1; t < n_off - 1; t++) if (q >= qbo[t]) b = t;
    return b;
}
__device__ __forceinline__ uint32_t smem_u32(const void* p) {
    uint32_t a;
    asm("{ .reg .u64 t; cvta.to.shared.u64 t, %1; cvt.u32.u64 %0, t; }" : "=r"(a) : "l"(p));
    return a;
}
__device__ __forceinline__ uint32_t bf2(float a, float b) {
    __nv_bfloat162 h = __floats2bfloat162_rn(a, b);
    return *(uint32_t*)&h;
}
__device__ __forceinline__ float bflo(float x, __nv_bfloat16 hi) {
    return x - __bfloat162float(hi);
}
__device__ __forceinline__ void ldsm_x4(uint32_t addr, uint32_t& r0, uint32_t& r1, uint32_t& r2, uint32_t& r3) {
    asm volatile("ldmatrix.sync.aligned.m8n8.x4.shared.b16 {%0,%1,%2,%3}, [%4];"
                 : "=r"(r0), "=r"(r1), "=r"(r2), "=r"(r3) : "r"(addr));
}
__device__ __forceinline__ void mma_bf16(float* c, uint32_t a0, uint32_t a1, uint32_t a2, uint32_t a3,
                                         uint32_t b0, uint32_t b1) {
    asm volatile("mma.sync.aligned.m16n8k16.row.col.f32.bf16.bf16.f32 "
                 "{%0,%1,%2,%3}, {%4,%5,%6,%7}, {%8,%9}, {%0,%1,%2,%3};"
                 : "+f"(c[0]), "+f"(c[1]), "+f"(c[2]), "+f"(c[3])
                 : "r"(a0), "r"(a1), "r"(a2), "r"(a3), "r"(b0), "r"(b1));
}

// ---------------- precompute ----------------
__global__ void copy_x_kernel(const float* __restrict__ src, int n) {
    int i = blockIdx.x * blockDim.x + threadIdx.x;
    if (i < n) g_x[i] = src[i];
}

__global__ void build_wt_kernel(const float* __restrict__ Wk, const float* __restrict__ Wv, int nl) {
    int id = blockIdx.x * blockDim.x + threadIdx.x;
    if (id >= nl * 256 * 128) return;
    int li = id / (256 * 128);
    int r  = id % (256 * 128);
    int n = r / 128, k = r % 128;
    float w = (n < 128) ? Wk[li*DM*DM + k*DM + n] : Wv[li*DM*DM + k*DM + (n - 128)];
    __nv_bfloat16 hi = __float2bfloat16(w);
    g_WBhi[id] = hi;
    g_WBlo[id] = __float2bfloat16(w - __bfloat162float(hi));
}

// cos/sin tables per (level, axis, integer coord)
__global__ void build_ktab_kernel(const int* __restrict__ shapes) {
    int id = blockIdx.x * blockDim.x + threadIdx.x;
    if (id >= 4 * 2 * 264) return;
    int l = id / (2 * 264);
    int axis = (id / 264) & 1;
    int gidx = id % 264;
    int g = gidx - 4;
    float scale = (float)shapes[2*l + axis] / (float)shapes[axis];
    float kp = ((float)g + 0.5f) / scale;
    float* t = &g_ktab[(size_t)id * 8];
    #pragma unroll
    for (int f = 0; f < 4; f++) {
        float a = kp * c_invfreq[f];
        t[f] = cosf(a);
        t[4 + f] = sinf(a);
    }
}

__global__ void build_rowsrc_kernel(const float* __restrict__ qpos,
                                    const int* __restrict__ qbo, int n_off,
                                    int R123, int R) {
    int e = blockIdx.x * blockDim.x + threadIdx.x;
    if (e >= R) return;
    int src;
    if (e < R123) {
        int b = e / PER_B, r = e % PER_B;
        int l, i, j;
        if (r < 16384)      { l = 1; i = r >> 7; j = r & 127; }
        else if (r < 20480) { int rr = r - 16384; l = 2; i = rr >> 6; j = rr & 63; }
        else                { int rr = r - 20480; l = 3; i = rr >> 5; j = rr & 31; }
        src = ((b * 256 + i) * 256 + j) * 4 + l;
    } else {
        int e2 = e - R123;
        int q = e2 / 9, t = e2 % 9;
        int b = batch_of(q, qbo, n_off);
        float p0 = qpos[2*q], p1 = qpos[2*q+1];
        int c0 = (int)floorf(p0), c1 = (int)floorf(p1);
        int gi = c0 + t / 3 - 1, gj = c1 + t % 3 - 1;
        gi = min(max(gi, 0), 255); gj = min(max(gj, 0), 255);
        src = ((b * 256 + gi) * 256 + gj) * 4 + 0;
    }
    g_rowsrc[e] = src;
}

__global__ void build_keys_kernel(const float* __restrict__ qpos,
                                  const int* __restrict__ qbo, int n_off,
                                  const int* __restrict__ shapes,
                                  int N, int R123) {
    int id = blockIdx.x * blockDim.x + threadIdx.x;
    if (id >= N * KTOT) return;
    int q = id / KTOT, k = id % KTOT;
    int l, t, d;
    if      (k < 9)  { l = 0; t = k;      d = 3; }
    else if (k < 34) { l = 1; t = k - 9;  d = 5; }
    else if (k < 83) { l = 2; t = k - 34; d = 7; }
    else             { l = 3; t = k - 83; d = 9; }
    int Hl = shapes[2*l], Wl = shapes[2*l+1];
    float sh = (float)Hl / (float)shapes[0];
    float sw = (float)Wl / (float)shapes[1];
    float p0 = qpos[2*q], p1 = qpos[2*q+1];
    int c0 = (int)floorf(p0 * sh), c1 = (int)floorf(p1 * sw);
    int gi = c0 + t / d - d / 2;
    int gj = c1 + t % d - d / 2;
    int valid = (gi >= 0 && gi < Hl && gj >= 0 && gj < Wl);
    int ci = min(max(gi, 0), Hl - 1), cj = min(max(gj, 0), Wl - 1);
    int b = batch_of(q, qbo, n_off);
    int idx;
    if (l == 0) idx = R123 + q * 9 + t;
    else {
        int base = (l == 1) ? 0 : (l == 2) ? 16384 : 20480;
        idx = b * PER_B + base + ci * Wl + cj;
    }
    g_kidx[id] = idx;
    g_kval[id] = valid;
    const float* ti = &g_ktab[(size_t)((l * 2 + 0) * 264 + (gi + 4)) * 8];
    const float* tj = &g_ktab[(size_t)((l * 2 + 1) * 264 + (gj + 4)) * 8];
    float* cs = &g_kcs[(size_t)id * 16];
    #pragma unroll
    for (int f = 0; f < 4; f++) {
        cs[f]      = ti[f];      cs[8  + f] = ti[4 + f];
        cs[4 + f]  = tj[f];      cs[12 + f] = tj[4 + f];
    }
}

__global__ void build_qcs_kernel(const float* __restrict__ qpos, int N) {
    int q = blockIdx.x * blockDim.x + threadIdx.x;
    if (q >= N) return;
    float p0 = qpos[2*q], p1 = qpos[2*q+1];
    float* cs = &g_qcs[q * 16];
    #pragma unroll
    for (int f = 0; f < 4; f++) {
        float a0 = p0 * c_invfreq[f];
        float a1 = p1 * c_invfreq[f];
        cs[f]      = cosf(a0);  cs[8  + f] = sinf(a0);
        cs[4 + f]  = cosf(a1);  cs[12 + f] = sinf(a1);
    }
}

// ---------------- mma.sync KV projection ----------------
#define A_STR 136
#define B_STR 40
#define OFF_AHI 0
#define OFF_ALO 34816
#define OFF_BHI 69632
#define OFF_BLO 79872
#define SM_MMA_TOTAL 90112

__global__ void __launch_bounds__(256, 2)
kvproj_mma_kernel(const float* __restrict__ fm, int li, int R) {
    extern __shared__ char smem[];
    uint32_t sbase = smem_u32(smem);
    int tid = threadIdx.x;
    int wid = tid >> 5, lane = tid & 31;
    int wm = wid & 3, wn = wid >> 2;        // warp tile: rows wm*32, cols wn*64
    int row0 = blockIdx.x * 128;

    // ---- phase 1: gather + convert A (128 rows x 128 k) to bf16 hi/lo smem ----
    #pragma unroll
    for (int it = 0; it < 16; it++) {
        int idx = tid + 256 * it;            // 0..4095 float4s
        int r = idx >> 5, c4 = idx & 31;
        int row = row0 + r; if (row >= R) row = R - 1;
        int src = g_rowsrc[row];
        float4 v = *(const float4*)(fm + (size_t)src * 128 + c4 * 4);
        __nv_bfloat16 hx = __float2bfloat16(v.x);
        __nv_bfloat16 hy = __float2bfloat16(v.y);
        __nv_bfloat16 hz = __float2bfloat16(v.z);
        __nv_bfloat16 hw = __float2bfloat16(v.w);
        uint32_t h01 = ((uint32_t)*(uint16_t*)&hy << 16) | *(uint16_t*)&hx;
        uint32_t h23 = ((uint32_t)*(uint16_t*)&hw << 16) | *(uint16_t*)&hz;
        uint32_t l01 = bf2(bflo(v.x, hx), bflo(v.y, hy));
        uint32_t l23 = bf2(bflo(v.z, hz), bflo(v.w, hw));
        uint32_t off = (uint32_t)(r * A_STR + c4 * 4) * 2;
        *(uint2*)(smem + OFF_AHI + off) = make_uint2(h01, h23);
        *(uint2*)(smem + OFF_ALO + off) = make_uint2(l01, l23);
    }

    const __nv_bfloat16* wbh = g_WBhi + (size_t)li * 256 * 128;
    const __nv_bfloat16* wbl = g_WBlo + (size_t)li * 256 * 128;

    for (int h = 0; h < 2; h++) {
        float acc[2][8][4];
        #pragma unroll
        for (int i = 0; i < 2; i++)
            #pragma unroll
            for (int j = 0; j < 8; j++)
                #pragma unroll
                for (int e = 0; e < 4; e++) acc[i][j][e] = 0.f;

        for (int c = 0; c < 4; c++) {
            __syncthreads();
            #pragma unroll
            for (int it = 0; it < 2; it++) {
                int idx = tid + 256 * it;            // 0..511
                int n = idx >> 2, kk = (idx & 3) * 8;
                const __nv_bfloat16* sh = wbh + ((size_t)(h * 128 + n)) * 128 + c * 32 + kk;
                const __nv_bfloat16* sl = wbl + ((size_t)(h * 128 + n)) * 128 + c * 32 + kk;
                uint32_t off = (uint32_t)(n * B_STR + kk) * 2;
                *(uint4*)(smem + OFF_BHI + off) = *(const uint4*)sh;
                *(uint4*)(smem + OFF_BLO + off) = *(const uint4*)sl;
            }
            __syncthreads();

            #pragma unroll
            for (int s = 0; s < 2; s++) {
                uint32_t ah[2][4], al[2][4];
                #pragma unroll
                for (int i = 0; i < 2; i++) {
                    uint32_t arow = wm * 32 + i * 16 + (lane & 15);
                    uint32_t akol = c * 32 + s * 16 + ((lane >> 4) << 3);
                    uint32_t aoff = (arow * A_STR + akol) * 2;
                    ldsm_x4(sbase + OFF_AHI + aoff, ah[i][0], ah[i][1], ah[i][2], ah[i][3]);
                    ldsm_x4(sbase + OFF_ALO + aoff, al[i][0], al[i][1], al[i][2], al[i][3]);
                }
                #pragma unroll
                for (int jj = 0; jj < 4; jj++) {
                    int m = lane >> 3, w8 = lane & 7;
                    uint32_t bn = wn * 64 + (2 * jj + (m >> 1)) * 8 + w8;
                    uint32_t bk = s * 16 + (m & 1) * 8;
                    uint32_t boff = (bn * B_STR + bk) * 2;
                    uint32_t bh0, bh1, bh2, bh3, bl0, bl1, bl2, bl3;
                    ldsm_x4(sbase + OFF_BHI + boff, bh0, bh1, bh2, bh3);
                    ldsm_x4(sbase + OFF_BLO + boff, bl0, bl1, bl2, bl3);
                    #pragma unroll
                    for (int i = 0; i < 2; i++) {
                        mma_bf16(acc[i][2*jj],   ah[i][0], ah[i][1], ah[i][2], ah[i][3], bh0, bh1);
                        mma_bf16(acc[i][2*jj],   ah[i][0], ah[i][1], ah[i][2], ah[i][3], bl0, bl1);
                        mma_bf16(acc[i][2*jj],   al[i][0], al[i][1], al[i][2], al[i][3], bh0, bh1);
                        mma_bf16(acc[i][2*jj+1], ah[i][0], ah[i][1], ah[i][2], ah[i][3], bh2, bh3);
                        mma_bf16(acc[i][2*jj+1], ah[i][0], ah[i][1], ah[i][2], ah[i][3], bl2, bl3);
                        mma_bf16(acc[i][2*jj+1], al[i][0], al[i][1], al[i][2], al[i][3], bh2, bh3);
                    }
                }
            }
        }
        float* dstbase = h ? g_Vc : g_Kc;
        #pragma unroll
        for (int i = 0; i < 2; i++) {
            int rA = row0 + wm * 32 + i * 16 + (lane >> 2);
            int rB = rA + 8;
            #pragma unroll
            for (int j = 0; j < 8; j++) {
                int col = wn * 64 + j * 8 + (lane & 3) * 2;
                if (rA < R) *(float2*)(dstbase + (size_t)rA * 128 + col) = make_float2(acc[i][j][0], acc[i][j][1]);
                if (rB < R) *(float2*)(dstbase + (size_t)rB * 128 + col) = make_float2(acc[i][j][2], acc[i][j][3]);
            }
        }
    }
}

// ---------------- per-layer kernels (per-query shapes — max parallelism) ----------------
__global__ void ln_qproj_kernel(const float* __restrict__ lg, const float* __restrict__ lb,
                                const float* __restrict__ Wq) {
    int q = blockIdx.x, tid = threadIdx.x;
    int lane = tid & 31, w = tid >> 5;
    __shared__ float sh[128];
    __shared__ float sraw[128];
    __shared__ float red[8];
    float x = g_x[q*DM + tid];
    float s1 = x, s2 = x * x;
    #pragma unroll
    for (int o = 16; o; o >>= 1) {
        s1 += __shfl_xor_sync(0xffffffffu, s1, o);
        s2 += __shfl_xor_sync(0xffffffffu, s2, o);
    }
    if (lane == 0) { red[w] = s1; red[4 + w] = s2; }
    __syncthreads();
    float mean = (red[0] + red[1] + red[2] + red[3]) * (1.f / 128.f);
    float var  = (red[4] + red[5] + red[6] + red[7]) * (1.f / 128.f) - mean * mean;
    float hval = (x - mean) * rsqrtf(var + 1e-5f) * lg[tid] + lb[tid];
    sh[tid] = hval;
    __syncthreads();
    float acc = 0.f;
    #pragma unroll 8
    for (int i = 0; i < 128; i++) acc += sh[i] * Wq[i * DM + tid];
    sraw[tid] = acc;
    __syncthreads();
    int p = (tid >> 1) & 7;
    float c = g_qcs[q*16 + p], s = g_qcs[q*16 + 8 + p];
    float x1 = sraw[tid & ~1];
    float x2 = sraw[tid |  1];
    g_q[q*DM + tid] = (tid & 1) ? (x1 * s + x2 * c) : (x1 * c - x2 * s);
}

__global__ void attn_kernel() {
    int q = blockIdx.x, tid = threadIdx.x;
    int lane = tid & 31, w = tid >> 5;
    __shared__ float sq[128];
    __shared__ float ssc[8 * KTOT];
    __shared__ int   skidx[KTOT];
    sq[tid] = g_q[q*DM + tid];
    for (int k = tid; k < KTOT; k += 128) skidx[k] = g_kidx[q*KTOT + k];
    __syncthreads();
    float4 qv = *(const float4*)&sq[lane * 4];
    for (int k = w; k < KTOT; k += 4) {
        int idx = skidx[k];
        float4 kv = *(const float4*)&g_Kc[(size_t)idx*DM + lane*4];
        const float* cs = &g_kcs[(size_t)((size_t)q*KTOT + k) * 16];
        float csv = (lane < 16) ? cs[lane] : 0.f;
        int m = lane & 3;
        float c0 = __shfl_sync(0xffffffffu, csv, 2*m);
        float s0 = __shfl_sync(0xffffffffu, csv, 8 + 2*m);
        float c1 = __shfl_sync(0xffffffffu, csv, 2*m + 1);
        float s1 = __shfl_sync(0xffffffffu, csv, 9 + 2*m);
        float r0 = kv.x*c0 - kv.y*s0;
        float r1 = kv.x*s0 + kv.y*c0;
        float r2 = kv.z*c1 - kv.w*s1;
        float r3 = kv.z*s1 + kv.w*c1;
        float ps = r0*qv.x + r1*qv.y + r2*qv.z + r3*qv.w;
        ps += __shfl_xor_sync(0xffffffffu, ps, 1);
        ps += __shfl_xor_sync(0xffffffffu, ps, 2);
        if ((lane & 3) == 0) {
            int h = lane >> 2;
            int val = g_kval[q*KTOT + k];
            ssc[h*KTOT + k] = val ? ps * 0.25f : -1.0e9f;
        }
    }
    __syncthreads();
    #pragma unroll
    for (int hh = 0; hh < 2; hh++) {
        int h = w * 2 + hh;
        float mx = -3.0e38f;
        for (int k = lane; k < KTOT; k += 32) mx = fmaxf(mx, ssc[h*KTOT + k]);
        #pragma unroll
        for (int o = 16; o; o >>= 1) mx = fmaxf(mx, __shfl_xor_sync(0xffffffffu, mx, o));
        float sum = 0.f;
        for (int k = lane; k < KTOT; k += 32) {
            float e = expf(ssc[h*KTOT + k] - mx);
            ssc[h*KTOT + k] = e;
            sum += e;
        }
        #pragma unroll
        for (int o = 16; o; o >>= 1) sum += __shfl_xor_sync(0xffffffffu, sum, o);
        float inv = 1.f / sum;
        for (int k = lane; k < KTOT; k += 32) ssc[h*KTOT + k] *= inv;
    }
    __syncthreads();
    int h = tid >> 4;
    float acc = 0.f;
    #pragma unroll 4
    for (int k = 0; k < KTOT; k++)
        acc += ssc[h*KTOT + k] * g_Vc[(size_t)skidx[k]*DM + tid];
    g_o[q*DM + tid] = acc;
}

__global__ void oproj_ln2_kernel(const float* __restrict__ Wo,
                                 const float* __restrict__ lg, const float* __restrict__ lb) {
    int q = blockIdx.x, tid = threadIdx.x;
    int lane = tid & 31, w = tid >> 5;
    __shared__ float so[128];
    __shared__ float red[8];
    so[tid] = g_o[q*DM + tid];
    __syncthreads();
    float acc = 0.f;
    #pragma unroll 8
    for (int i = 0; i < 128; i++) acc += so[i] * Wo[i * DM + tid];
    float x = g_x[q*DM + tid] + acc;
    g_x[q*DM + tid] = x;
    float s1 = x, s2 = x * x;
    #pragma unroll
    for (int o = 16; o; o >>= 1) {
        s1 += __shfl_xor_sync(0xffffffffu, s1, o);
        s2 += __shfl_xor_sync(0xffffffffu, s2, o);
    }
    if (lane == 0) { red[w] = s1; red[4 + w] = s2; }
    __syncthreads();
    float mean = (red[0] + red[1] + red[2] + red[3]) * (1.f / 128.f);
    float var  = (red[4] + red[5] + red[6] + red[7]) * (1.f / 128.f) - mean * mean;
    g_h[q*DM + tid] = (x - mean) * rsqrtf(var + 1e-5f) * lg[tid] + lb[tid];
}

// t = gelu(h @ W1 + b1), 8 queries per block, 256 threads.
__global__ void ffn1_kernel(const float* __restrict__ W1, const float* __restrict__ pb, int N) {
    int q0 = blockIdx.x * 8, tid = threadIdx.x;
    __shared__ float sh2[8][128];
    for (int i = tid; i < 1024; i += 256) {
        int r = i >> 7, c = i & 127;
        int q = q0 + r;
        sh2[r][c] = (q < N) ? g_h[q*DM + c] : 0.f;
    }
    __syncthreads();
    ull acc0[4], acc1[4];
    #pragma unroll
    for (int p = 0; p < 4; p++) { acc0[p] = 0ull; acc1[p] = 0ull; }
    #pragma unroll 4
    for (int i = 0; i < 128; i++) {
        ull w0 = pack2(W1[i*512 + tid]);
        ull w1 = pack2(W1[i*512 + 256 + tid]);
        #pragma unroll
        for (int p = 0; p < 4; p++) {
            ull hp = packab(sh2[2*p][i], sh2[2*p+1][i]);
            acc0[p] = fma2(hp, w0, acc0[p]);
            acc1[p] = fma2(hp, w1, acc1[p]);
        }
    }
    float bb0 = pb[tid], bb1 = pb[256 + tid];
    #pragma unroll
    for (int p = 0; p < 4; p++) {
        float a0, a1, b0v, b1v;
        unpack2(acc0[p], a0, a1);
        unpack2(acc1[p], b0v, b1v);
        int qA = q0 + 2*p, qB = q0 + 2*p + 1;
        if (qA < N) { g_t[qA*512 + tid] = gelu_tanh(a0 + bb0); g_t[qA*512 + 256 + tid] = gelu_tanh(b0v + bb1); }
        if (qB < N) { g_t[qB*512 + tid] = gelu_tanh(a1 + bb0); g_t[qB*512 + 256 + tid] = gelu_tanh(b1v + bb1); }
    }
}

// x += t @ W2 + b2, 8 queries per block, 128 threads.
__global__ void ffn2_kernel(const float* __restrict__ W2, const float* __restrict__ pb, int N) {
    int q0 = blockIdx.x * 8, tid = threadIdx.x;
    __shared__ float st[8][512];
    for (int i = tid; i < 4096; i += 128) {
        int r = i >> 9, c = i & 511;
        int q = q0 + r;
        st[r][c] = (q < N) ? g_t[q*512 + c] : 0.f;
    }
    __syncthreads();
    ull acc[4];
    #pragma unroll
    for (int p = 0; p < 4; p++) acc[p] = 0ull;
    #pragma unroll 4
    for (int i = 0; i < 512; i++) {
        ull wv = pack2(W2[i*128 + tid]);
        #pragma unroll
        for (int p = 0; p < 4; p++) {
            ull tp = packab(st[2*p][i], st[2*p+1][i]);
            acc[p] = fma2(tp, wv, acc[p]);
        }
    }
    float bb = pb[tid];
    #pragma unroll
    for (int p = 0; p < 4; p++) {
        float a0, a1;
        unpack2(acc[p], a0, a1);
        int qA = q0 + 2*p, qB = q0 + 2*p + 1;
        if (qA < N) g_x[qA*DM + tid] += a0 + bb;
        if (qB < N) g_x[qB*DM + tid] += a1 + bb;
    }
}

__global__ void logits_kernel(const float* __restrict__ fm, const float* __restrict__ qpos,
                              const int* __restrict__ qbo, int n_off,
                              const int* __restrict__ shapes, float* __restrict__ out) {
    int q = blockIdx.x, tid = threadIdx.x;
    int lane = tid & 31, w = tid >> 5;
    __shared__ float sx[128];
    __shared__ int sb;
    if (tid < 128) sx[tid] = g_x[q*DM + tid];
    if (tid == 0) sb = batch_of(q, qbo, n_off);
    __syncthreads();
    int H0 = shapes[0], W0 = shapes[1];
    float p0 = qpos[2*q], p1 = qpos[2*q+1];
    int c0 = (int)floorf(p0), c1 = (int)floorf(p1);
    float4 xv = *(const float4*)&sx[lane * 4];
    int b = sb;
    for (int pp = w; pp < 49; pp += 8) {
        int gi = c0 + pp / 7 - 3;
        int gj = c1 + pp % 7 - 3;
        bool valid = (gi >= 0 && gi < H0 && gj >= 0 && gj < W0);
        int ci = min(max(gi, 0), H0 - 1), cj = min(max(gj, 0), W0 - 1);
        const float* f = fm + ((((size_t)b * 256 + ci) * 256 + cj) * 4 + 0) * 128;
        float4 fv = *(const float4*)(f + lane * 4);
        float d = fv.x*xv.x + fv.y*xv.y + fv.z*xv.z + fv.w*xv.w;
        #pragma unroll
        for (int o = 16; o; o >>= 1) d += __shfl_xor_sync(0xffffffffu, d, o);
        if (lane == 0) out[q*49 + pp] = valid ? d : 0.f;
    }
}

// ---------------- launch ----------------
extern "C" void kernel_launch(void* const* d_in, const int* in_sizes, int n_in,
                              void* d_out, int out_size) {
    const float* queries = (const float*)d_in[0];
    const int*   qbo     = (const int*)  d_in[1];
    const float* qpos    = (const float*)d_in[2];
    const float* fm      = (const float*)d_in[3];
    const int*   shapes  = (const int*)  d_in[4];
    const float* Wq      = (const float*)d_in[5];
    const float* Wk      = (const float*)d_in[6];
    const float* Wv      = (const float*)d_in[7];
    const float* Wo      = (const float*)d_in[8];
    const float* ln1g    = (const float*)d_in[9];
    const float* ln1b    = (const float*)d_in[10];
    const float* ln2g    = (const float*)d_in[11];
    const float* ln2b    = (const float*)d_in[12];
    const float* W1      = (const float*)d_in[13];
    const float* b1      = (const float*)d_in[14];
    const float* W2      = (const float*)d_in[15];
    const float* b2      = (const float*)d_in[16];

    int N     = in_sizes[0] / DM;
    int n_off = in_sizes[1];
    int nl    = in_sizes[5] / (DM * DM);
    int B     = in_sizes[3] / (256 * 256 * 4 * DM);
    int R123  = B * PER_B;
    int R     = R123 + N * 9;
    int gridR = (R + 127) / 128;

    cudaFuncSetAttribute(kvproj_mma_kernel, cudaFuncAttributeMaxDynamicSharedMemorySize, SM_MMA_TOTAL);

    // ordering: kvproj at launch index 3 so the ncu window catches it
    build_rowsrc_kernel<<<(R + 255) / 256, 256>>>(qpos, qbo, n_off, R123, R);
    build_wt_kernel<<<(nl*256*128 + 255) / 256, 256>>>(Wk, Wv, nl);
    build_ktab_kernel<<<(4*2*264 + 127) / 128, 128>>>(shapes);
    kvproj_mma_kernel<<<gridR, 256, SM_MMA_TOTAL>>>(fm, 0, R);
    build_qcs_kernel<<<(N + 127) / 128, 128>>>(qpos, N);
    copy_x_kernel<<<(N*DM + 255) / 256, 256>>>(queries, N * DM);
    build_keys_kernel<<<(N*KTOT + 127) / 128, 128>>>(qpos, qbo, n_off, shapes, N, R123);

    for (int li = 0; li < nl; li++) {
        if (li > 0)
            kvproj_mma_kernel<<<gridR, 256, SM_MMA_TOTAL>>>(fm, li, R);
        ln_qproj_kernel<<<N, 128>>>(ln1g + li*DM, ln1b + li*DM, Wq + li*DM*DM);
        attn_kernel<<<N, 128>>>();
        oproj_ln2_kernel<<<N, 128>>>(Wo + li*DM*DM, ln2g + li*DM, ln2b + li*DM);
        ffn1_kernel<<<(N + 7) / 8, 256>>>(W1 + li*DM*512, b1 + li*512, N);
        ffn2_kernel<<<(N + 7) / 8, 128>>>(W2 + li*512*DM, b2 + li*DM, N);
    }
    logits_kernel<<<N, 256>>>(fm, qpos, qbo, n_off, shapes, (float*)d_out);
}

// round 10
// speedup vs baseline: 1.5876x; 1.4666x over previous
#include <cuda_runtime.h>
#include <cuda_bf16.h>
#include <math.h>
#include <stdint.h>

#define DM   128
#define NH   8
#define HD   16
#define KTOT 164          // 9 + 25 + 49 + 81
#define PER_B 21504       // 128*128 + 64*64 + 32*32
#define MAXN 2048
#define MAXROWS (2*PER_B + MAXN*9)
#define MAXL 4

typedef unsigned long long ull;

// ---------------- device scratch ----------------
__device__ float g_x  [MAXN*DM];
__device__ float g_h  [MAXN*DM];
__device__ float g_q  [MAXN*DM];
__device__ float g_o  [MAXN*DM];
__device__ float g_qcs[MAXN*16];
__device__ int   g_kidx[MAXN*KTOT];
__device__ int   g_kval[MAXN*KTOT];
__device__ int   g_rowsrc[MAXROWS];
__device__ float g_rcs[MAXROWS*16];              // per-row RoPE cos/sin
__device__ float g_Kc[(size_t)MAXROWS*DM];
__device__ float g_Vc[(size_t)MAXROWS*DM];
__device__ __nv_bfloat16 g_WBhi[MAXL*256*128];   // [layer][n: Wk|Wv][k]
__device__ __nv_bfloat16 g_WBlo[MAXL*256*128];
__device__ float g_ktab[4*2*264*8];              // [level][axis][g+4][4cos,4sin]

__device__ __constant__ float c_invfreq[4] = {1.0f, 0.56234132519f, 0.316227766017f, 0.177827941004f};

// ---------------- helpers ----------------
__device__ __forceinline__ ull fma2(ull a, ull b, ull c) {
    ull d; asm("fma.rn.f32x2 %0, %1, %2, %3;" : "=l"(d) : "l"(a), "l"(b), "l"(c)); return d;
}
__device__ __forceinline__ ull pack2(float f) {
    ull r; asm("mov.b64 %0, {%1, %1};" : "=l"(r) : "r"(__float_as_uint(f))); return r;
}
__device__ __forceinline__ ull packab(float a, float b) {
    ull r; asm("mov.b64 %0, {%1, %2};" : "=l"(r) : "r"(__float_as_uint(a)), "r"(__float_as_uint(b))); return r;
}
__device__ __forceinline__ void unpack2(ull v, float& lo, float& hi) {
    unsigned int a, b; asm("mov.b64 {%0, %1}, %2;" : "=r"(a), "=r"(b) : "l"(v));
    lo = __uint_as_float(a); hi = __uint_as_float(b);
}
__device__ __forceinline__ float gelu_tanh(float v) {
    float u = 0.7978845608028654f * (v + 0.044715f * v * v * v);
    return 0.5f * v * (1.f + tanhf(u));
}
__device__ __forceinline__ int batch_of(int q, const int* qbo, int n_off) {
    int b = 0;
    for (int t = 1; t < n_off - 1; t++) if (q >= qbo[t]) b = t;
    return b;
}
__device__ __forceinline__ uint32_t smem_u32(const void* p) {
    uint32_t a;
    asm("{ .reg .u64 t; cvta.to.shared.u64 t, %1; cvt.u32.u64 %0, t; }" : "=r"(a) : "l"(p));
    return a;
}
__device__ __forceinline__ uint32_t bf2(float a, float b) {
    __nv_bfloat162 h = __floats2bfloat162_rn(a, b);
    return *(uint32_t*)&h;
}
__device__ __forceinline__ float bflo(float x, __nv_bfloat16 hi) {
    return x - __bfloat162float(hi);
}
__device__ __forceinline__ void ldsm_x4(uint32_t addr, uint32_t& r0, uint32_t& r1, uint32_t& r2, uint32_t& r3) {
    asm volatile("ldmatrix.sync.aligned.m8n8.x4.shared.b16 {%0,%1,%2,%3}, [%4];"
                 : "=r"(r0), "=r"(r1), "=r"(r2), "=r"(r3) : "r"(addr));
}
__device__ __forceinline__ void mma_bf16(float* c, uint32_t a0, uint32_t a1, uint32_t a2, uint32_t a3,
                                         uint32_t b0, uint32_t b1) {
    asm volatile("mma.sync.aligned.m16n8k16.row.col.f32.bf16.bf16.f32 "
                 "{%0,%1,%2,%3}, {%4,%5,%6,%7}, {%8,%9}, {%0,%1,%2,%3};"
                 : "+f"(c[0]), "+f"(c[1]), "+f"(c[2]), "+f"(c[3])
                 : "r"(a0), "r"(a1), "r"(a2), "r"(a3), "r"(b0), "r"(b1));
}

// ---------------- LN1 + Qproj + RoPE body (per-query, 128 threads) ----------------
__device__ void ln_qproj_body(int q, const float* __restrict__ lg, const float* __restrict__ lb,
                              const float* __restrict__ Wq) {
    int tid = threadIdx.x;
    int lane = tid & 31, w = tid >> 5;
    __shared__ float sh[128];
    __shared__ float sraw[128];
    __shared__ float red[8];
    float x = g_x[q*DM + tid];
    float s1 = x, s2 = x * x;
    #pragma unroll
    for (int o = 16; o; o >>= 1) {
        s1 += __shfl_xor_sync(0xffffffffu, s1, o);
        s2 += __shfl_xor_sync(0xffffffffu, s2, o);
    }
    if (lane == 0) { red[w] = s1; red[4 + w] = s2; }
    __syncthreads();
    float mean = (red[0] + red[1] + red[2] + red[3]) * (1.f / 128.f);
    float var  = (red[4] + red[5] + red[6] + red[7]) * (1.f / 128.f) - mean * mean;
    sh[tid] = (x - mean) * rsqrtf(var + 1e-5f) * lg[tid] + lb[tid];
    __syncthreads();
    float acc = 0.f;
    #pragma unroll 8
    for (int i = 0; i < 128; i++) acc += sh[i] * Wq[i * DM + tid];
    sraw[tid] = acc;
    __syncthreads();
    int p = (tid >> 1) & 7;
    float c = g_qcs[q*16 + p], s = g_qcs[q*16 + 8 + p];
    float x1 = sraw[tid & ~1];
    float x2 = sraw[tid |  1];
    g_q[q*DM + tid] = (tid & 1) ? (x1 * s + x2 * c) : (x1 * c - x2 * s);
}

// ---------------- fused prep kernel #1 (256 threads) ----------------
// sections: copy_x | rowsrc | wt-split | ktab | qcs
__global__ void prep1_kernel(const float* __restrict__ queries,
                             const float* __restrict__ qpos,
                             const int* __restrict__ qbo, int n_off,
                             const int* __restrict__ shapes,
                             const float* __restrict__ Wk, const float* __restrict__ Wv,
                             int N, int nl, int R123, int R,
                             int o1, int o2, int o3, int o4) {
    int bid = blockIdx.x, tid = threadIdx.x;
    if (bid < o1) {                                      // copy_x
        int i = bid * 256 + tid;
        if (i < N * DM) g_x[i] = queries[i];
    } else if (bid < o2) {                               // rowsrc
        int e = (bid - o1) * 256 + tid;
        if (e >= R) return;
        int src;
        if (e < R123) {
            int b = e / PER_B, r = e % PER_B;
            int l, i, j;
            if (r < 16384)      { l = 1; i = r >> 7; j = r & 127; }
            else if (r < 20480) { int rr = r - 16384; l = 2; i = rr >> 6; j = rr & 63; }
            else                { int rr = r - 20480; l = 3; i = rr >> 5; j = rr & 31; }
            src = ((b * 256 + i) * 256 + j) * 4 + l;
        } else {
            int e2 = e - R123;
            int q = e2 / 9, t = e2 % 9;
            int b = batch_of(q, qbo, n_off);
            int c0 = (int)floorf(qpos[2*q]), c1 = (int)floorf(qpos[2*q+1]);
            int gi = min(max(c0 + t / 3 - 1, 0), 255);
            int gj = min(max(c1 + t % 3 - 1, 0), 255);
            src = ((b * 256 + gi) * 256 + gj) * 4 + 0;
        }
        g_rowsrc[e] = src;
    } else if (bid < o3) {                               // wt split
        int id = (bid - o2) * 256 + tid;
        if (id >= nl * 256 * 128) return;
        int li = id / (256 * 128);
        int r  = id % (256 * 128);
        int n = r / 128, k = r % 128;
        float w = (n < 128) ? Wk[li*DM*DM + k*DM + n] : Wv[li*DM*DM + k*DM + (n - 128)];
        __nv_bfloat16 hi = __float2bfloat16(w);
        g_WBhi[id] = hi;
        g_WBlo[id] = __float2bfloat16(w - __bfloat162float(hi));
    } else if (bid < o4) {                               // ktab
        int id = (bid - o3) * 256 + tid;
        if (id >= 4 * 2 * 264) return;
        int l = id / (2 * 264);
        int axis = (id / 264) & 1;
        int g = (id % 264) - 4;
        float scale = (float)shapes[2*l + axis] / (float)shapes[axis];
        float kp = ((float)g + 0.5f) / scale;
        float* t = &g_ktab[(size_t)id * 8];
        #pragma unroll
        for (int f = 0; f < 4; f++) {
            float a = kp * c_invfreq[f];
            t[f] = cosf(a);
            t[4 + f] = sinf(a);
        }
    } else {                                             // qcs
        int q = (bid - o4) * 256 + tid;
        if (q >= N) return;
        float p0 = qpos[2*q], p1 = qpos[2*q+1];
        float* cs = &g_qcs[q * 16];
        #pragma unroll
        for (int f = 0; f < 4; f++) {
            float a0 = p0 * c_invfreq[f];
            float a1 = p1 * c_invfreq[f];
            cs[f]      = cosf(a0);  cs[8  + f] = sinf(a0);
            cs[4 + f]  = cosf(a1);  cs[12 + f] = sinf(a1);
        }
    }
}

// ---------------- fused prep kernel #2 (128 threads) ----------------
// sections: ln_qproj(layer0) | build_keys | build_rcs
__global__ void prep2_kernel(const float* __restrict__ lg, const float* __restrict__ lb,
                             const float* __restrict__ Wq,
                             const float* __restrict__ qpos,
                             const int* __restrict__ qbo, int n_off,
                             const int* __restrict__ shapes,
                             int N, int R123, int R, int KB) {
    int bid = blockIdx.x, tid = threadIdx.x;
    if (bid < N) {                                       // ln_qproj layer 0
        ln_qproj_body(bid, lg, lb, Wq);
    } else if (bid < N + KB) {                           // build_keys (idx + valid only)
        int id = (bid - N) * 128 + tid;
        if (id >= N * KTOT) return;
        int q = id / KTOT, k = id % KTOT;
        int l, t, d;
        if      (k < 9)  { l = 0; t = k;      d = 3; }
        else if (k < 34) { l = 1; t = k - 9;  d = 5; }
        else if (k < 83) { l = 2; t = k - 34; d = 7; }
        else             { l = 3; t = k - 83; d = 9; }
        int Hl = shapes[2*l], Wl = shapes[2*l+1];
        float sh = (float)Hl / (float)shapes[0];
        float sw = (float)Wl / (float)shapes[1];
        int c0 = (int)floorf(qpos[2*q] * sh), c1 = (int)floorf(qpos[2*q+1] * sw);
        int gi = c0 + t / d - d / 2;
        int gj = c1 + t % d - d / 2;
        int valid = (gi >= 0 && gi < Hl && gj >= 0 && gj < Wl);
        int ci = min(max(gi, 0), Hl - 1), cj = min(max(gj, 0), Wl - 1);
        int b = batch_of(q, qbo, n_off);
        int idx;
        if (l == 0) idx = R123 + q * 9 + t;
        else {
            int base = (l == 1) ? 0 : (l == 2) ? 16384 : 20480;
            idx = b * PER_B + base + ci * Wl + cj;
        }
        g_kidx[id] = idx;
        g_kval[id] = valid;
    } else {                                             // build_rcs
        int e = (bid - N - KB) * 128 + tid;
        if (e >= R * 16) return;
        int row = e >> 4, idx = e & 15;
        int l, gi, gj;
        if (row < R123) {
            int b = row / PER_B, r = row % PER_B; (void)b;
            if (r < 16384)      { l = 1; gi = r >> 7; gj = r & 127; }
            else if (r < 20480) { int rr = r - 16384; l = 2; gi = rr >> 6; gj = rr & 63; }
            else                { int rr = r - 20480; l = 3; gi = rr >> 5; gj = rr & 31; }
        } else {
            int e2 = row - R123;
            int q = e2 / 9, t = e2 % 9;
            l = 0;
            gi = min(max((int)floorf(qpos[2*q])   + t / 3 - 1, 0), 255);
            gj = min(max((int)floorf(qpos[2*q+1]) + t % 3 - 1, 0), 255);
        }
        int trig = idx >> 3, p = idx & 7, axis = p >> 2, f = p & 3;
        int g = axis ? gj : gi;
        g_rcs[e] = g_ktab[(size_t)((l * 2 + axis) * 264 + (g + 4)) * 8 + trig * 4 + f];
    }
}

// standalone ln_qproj for layer >= 1
__global__ void ln_qproj_kernel(const float* __restrict__ lg, const float* __restrict__ lb,
                                const float* __restrict__ Wq) {
    ln_qproj_body(blockIdx.x, lg, lb, Wq);
}

// ---------------- mma.sync KV projection (rope fused into K epilogue) ----------------
#define A_STR 136
#define B_STR 40
#define OFF_AHI 0
#define OFF_ALO 34816
#define OFF_BHI 69632
#define OFF_BLO 79872
#define SM_MMA_TOTAL 90112

__global__ void __launch_bounds__(256, 2)
kvproj_mma_kernel(const float* __restrict__ fm, int li, int R) {
    extern __shared__ char smem[];
    uint32_t sbase = smem_u32(smem);
    int tid = threadIdx.x;
    int wid = tid >> 5, lane = tid & 31;
    int wm = wid & 3, wn = wid >> 2;
    int row0 = blockIdx.x * 128;

    #pragma unroll
    for (int it = 0; it < 16; it++) {
        int idx = tid + 256 * it;
        int r = idx >> 5, c4 = idx & 31;
        int row = row0 + r; if (row >= R) row = R - 1;
        int src = g_rowsrc[row];
        float4 v = *(const float4*)(fm + (size_t)src * 128 + c4 * 4);
        __nv_bfloat16 hx = __float2bfloat16(v.x);
        __nv_bfloat16 hy = __float2bfloat16(v.y);
        __nv_bfloat16 hz = __float2bfloat16(v.z);
        __nv_bfloat16 hw = __float2bfloat16(v.w);
        uint32_t h01 = ((uint32_t)*(uint16_t*)&hy << 16) | *(uint16_t*)&hx;
        uint32_t h23 = ((uint32_t)*(uint16_t*)&hw << 16) | *(uint16_t*)&hz;
        uint32_t l01 = bf2(bflo(v.x, hx), bflo(v.y, hy));
        uint32_t l23 = bf2(bflo(v.z, hz), bflo(v.w, hw));
        uint32_t off = (uint32_t)(r * A_STR + c4 * 4) * 2;
        *(uint2*)(smem + OFF_AHI + off) = make_uint2(h01, h23);
        *(uint2*)(smem + OFF_ALO + off) = make_uint2(l01, l23);
    }

    const __nv_bfloat16* wbh = g_WBhi + (size_t)li * 256 * 128;
    const __nv_bfloat16* wbl = g_WBlo + (size_t)li * 256 * 128;

    for (int h = 0; h < 2; h++) {
        float acc[2][8][4];
        #pragma unroll
        for (int i = 0; i < 2; i++)
            #pragma unroll
            for (int j = 0; j < 8; j++)
                #pragma unroll
                for (int e = 0; e < 4; e++) acc[i][j][e] = 0.f;

        for (int c = 0; c < 4; c++) {
            __syncthreads();
            #pragma unroll
            for (int it = 0; it < 2; it++) {
                int idx = tid + 256 * it;
                int n = idx >> 2, kk = (idx & 3) * 8;
                const __nv_bfloat16* sh = wbh + ((size_t)(h * 128 + n)) * 128 + c * 32 + kk;
                const __nv_bfloat16* sl = wbl + ((size_t)(h * 128 + n)) * 128 + c * 32 + kk;
                uint32_t off = (uint32_t)(n * B_STR + kk) * 2;
                *(uint4*)(smem + OFF_BHI + off) = *(const uint4*)sh;
                *(uint4*)(smem + OFF_BLO + off) = *(const uint4*)sl;
            }
            __syncthreads();

            #pragma unroll
            for (int s = 0; s < 2; s++) {
                uint32_t ah[2][4], al[2][4];
                #pragma unroll
                for (int i = 0; i < 2; i++) {
                    uint32_t arow = wm * 32 + i * 16 + (lane & 15);
                    uint32_t akol = c * 32 + s * 16 + ((lane >> 4) << 3);
                    uint32_t aoff = (arow * A_STR + akol) * 2;
                    ldsm_x4(sbase + OFF_AHI + aoff, ah[i][0], ah[i][1], ah[i][2], ah[i][3]);
                    ldsm_x4(sbase + OFF_ALO + aoff, al[i][0], al[i][1], al[i][2], al[i][3]);
                }
                #pragma unroll
                for (int jj = 0; jj < 4; jj++) {
                    int m = lane >> 3, w8 = lane & 7;
                    uint32_t bn = wn * 64 + (2 * jj + (m >> 1)) * 8 + w8;
                    uint32_t bk = s * 16 + (m & 1) * 8;
                    uint32_t boff = (bn * B_STR + bk) * 2;
                    uint32_t bh0, bh1, bh2, bh3, bl0, bl1, bl2, bl3;
                    ldsm_x4(sbase + OFF_BHI + boff, bh0, bh1, bh2, bh3);
                    ldsm_x4(sbase + OFF_BLO + boff, bl0, bl1, bl2, bl3);
                    #pragma unroll
                    for (int i = 0; i < 2; i++) {
                        mma_bf16(acc[i][2*jj],   ah[i][0], ah[i][1], ah[i][2], ah[i][3], bh0, bh1);
                        mma_bf16(acc[i][2*jj],   ah[i][0], ah[i][1], ah[i][2], ah[i][3], bl0, bl1);
                        mma_bf16(acc[i][2*jj],   al[i][0], al[i][1], al[i][2], al[i][3], bh0, bh1);
                        mma_bf16(acc[i][2*jj+1], ah[i][0], ah[i][1], ah[i][2], ah[i][3], bh2, bh3);
                        mma_bf16(acc[i][2*jj+1], ah[i][0], ah[i][1], ah[i][2], ah[i][3], bl2, bl3);
                        mma_bf16(acc[i][2*jj+1], al[i][0], al[i][1], al[i][2], al[i][3], bh2, bh3);
                    }
                }
            }
        }
        float* dstbase = h ? g_Vc : g_Kc;
        int pb = lane & 3;
        #pragma unroll
        for (int i = 0; i < 2; i++) {
            int rA = row0 + wm * 32 + i * 16 + (lane >> 2);
            int rB = rA + 8;
            if (h == 0) {
                // fused RoPE: pair (col, col+1) rotated by row's own cos/sin.
                // p = (4j + (lane&3)) & 7 -> j even: pb, j odd: pb+4
                float cA0 = g_rcs[rA*16 + pb],     sA0 = g_rcs[rA*16 + 8 + pb];
                float cA1 = g_rcs[rA*16 + 4 + pb], sA1 = g_rcs[rA*16 + 12 + pb];
                float cB0 = g_rcs[rB*16 + pb],     sB0 = g_rcs[rB*16 + 8 + pb];
                float cB1 = g_rcs[rB*16 + 4 + pb], sB1 = g_rcs[rB*16 + 12 + pb];
                #pragma unroll
                for (int j = 0; j < 8; j++) {
                    int col = wn * 64 + j * 8 + pb * 2;
                    float cc = (j & 1) ? cA1 : cA0, ss = (j & 1) ? sA1 : sA0;
                    float a0 = acc[i][j][0], a1 = acc[i][j][1];
                    if (rA < R) *(float2*)(dstbase + (size_t)rA * 128 + col) =
                        make_float2(a0 * cc - a1 * ss, a0 * ss + a1 * cc);
                    float cc2 = (j & 1) ? cB1 : cB0, ss2 = (j & 1) ? sB1 : sB0;
                    float b0 = acc[i][j][2], b1 = acc[i][j][3];
                    if (rB < R) *(float2*)(dstbase + (size_t)rB * 128 + col) =
                        make_float2(b0 * cc2 - b1 * ss2, b0 * ss2 + b1 * cc2);
                }
            } else {
                #pragma unroll
                for (int j = 0; j < 8; j++) {
                    int col = wn * 64 + j * 8 + pb * 2;
                    if (rA < R) *(float2*)(dstbase + (size_t)rA * 128 + col) = make_float2(acc[i][j][0], acc[i][j][1]);
                    if (rB < R) *(float2*)(dstbase + (size_t)rB * 128 + col) = make_float2(acc[i][j][2], acc[i][j][3]);
                }
            }
        }
    }
}

// ---------------- attention (K pre-rotated; plain dot products) ----------------
__global__ void attn_kernel() {
    int q = blockIdx.x, tid = threadIdx.x;
    int lane = tid & 31, w = tid >> 5;
    __shared__ float sq[128];
    __shared__ float ssc[8 * KTOT];
    __shared__ int   skidx[KTOT];
    sq[tid] = g_q[q*DM + tid];
    for (int k = tid; k < KTOT; k += 128) skidx[k] = g_kidx[q*KTOT + k];
    __syncthreads();
    float4 qv = *(const float4*)&sq[lane * 4];
    for (int k = w; k < KTOT; k += 4) {
        int idx = skidx[k];
        float4 kv = *(const float4*)&g_Kc[(size_t)idx*DM + lane*4];
        float ps = kv.x*qv.x + kv.y*qv.y + kv.z*qv.z + kv.w*qv.w;
        ps += __shfl_xor_sync(0xffffffffu, ps, 1);
        ps += __shfl_xor_sync(0xffffffffu, ps, 2);
        if ((lane & 3) == 0) {
            int h = lane >> 2;
            int val = g_kval[q*KTOT + k];
            ssc[h*KTOT + k] = val ? ps * 0.25f : -1.0e9f;
        }
    }
    __syncthreads();
    #pragma unroll
    for (int hh = 0; hh < 2; hh++) {
        int h = w * 2 + hh;
        float mx = -3.0e38f;
        for (int k = lane; k < KTOT; k += 32) mx = fmaxf(mx, ssc[h*KTOT + k]);
        #pragma unroll
        for (int o = 16; o; o >>= 1) mx = fmaxf(mx, __shfl_xor_sync(0xffffffffu, mx, o));
        float sum = 0.f;
        for (int k = lane; k < KTOT; k += 32) {
            float e = expf(ssc[h*KTOT + k] - mx);
            ssc[h*KTOT + k] = e;
            sum += e;
        }
        #pragma unroll
        for (int o = 16; o; o >>= 1) sum += __shfl_xor_sync(0xffffffffu, sum, o);
        float inv = 1.f / sum;
        for (int k = lane; k < KTOT; k += 32) ssc[h*KTOT + k] *= inv;
    }
    __syncthreads();
    int h = tid >> 4;
    float acc = 0.f;
    #pragma unroll 4
    for (int k = 0; k < KTOT; k++)
        acc += ssc[h*KTOT + k] * g_Vc[(size_t)skidx[k]*DM + tid];
    g_o[q*DM + tid] = acc;
}

__global__ void oproj_ln2_kernel(const float* __restrict__ Wo,
                                 const float* __restrict__ lg, const float* __restrict__ lb) {
    int q = blockIdx.x, tid = threadIdx.x;
    int lane = tid & 31, w = tid >> 5;
    __shared__ float so[128];
    __shared__ float red[8];
    so[tid] = g_o[q*DM + tid];
    __syncthreads();
    float acc = 0.f;
    #pragma unroll 8
    for (int i = 0; i < 128; i++) acc += so[i] * Wo[i * DM + tid];
    float x = g_x[q*DM + tid] + acc;
    g_x[q*DM + tid] = x;
    float s1 = x, s2 = x * x;
    #pragma unroll
    for (int o = 16; o; o >>= 1) {
        s1 += __shfl_xor_sync(0xffffffffu, s1, o);
        s2 += __shfl_xor_sync(0xffffffffu, s2, o);
    }
    if (lane == 0) { red[w] = s1; red[4 + w] = s2; }
    __syncthreads();
    float mean = (red[0] + red[1] + red[2] + red[3]) * (1.f / 128.f);
    float var  = (red[4] + red[5] + red[6] + red[7]) * (1.f / 128.f) - mean * mean;
    g_h[q*DM + tid] = (x - mean) * rsqrtf(var + 1e-5f) * lg[tid] + lb[tid];
}

// ---------------- fused FFN: x += gelu(h @ W1 + b1) @ W2 + b2.  8 q/block, 256 thr ----------------
__global__ void ffn_kernel(const float* __restrict__ W1, const float* __restrict__ b1v,
                           const float* __restrict__ W2, const float* __restrict__ b2v, int N) {
    int q0 = blockIdx.x * 8, tid = threadIdx.x;
    __shared__ float sh2[8][128];
    __shared__ float st[8][512];
    for (int i = tid; i < 1024; i += 256) {
        int r = i >> 7, c = i & 127;
        int q = q0 + r;
        sh2[r][c] = (q < N) ? g_h[q*DM + c] : 0.f;
    }
    __syncthreads();
    {
        ull acc0[4], acc1[4];
        #pragma unroll
        for (int p = 0; p < 4; p++) { acc0[p] = 0ull; acc1[p] = 0ull; }
        #pragma unroll 4
        for (int i = 0; i < 128; i++) {
            ull w0 = pack2(W1[i*512 + tid]);
            ull w1 = pack2(W1[i*512 + 256 + tid]);
            #pragma unroll
            for (int p = 0; p < 4; p++) {
                ull hp = packab(sh2[2*p][i], sh2[2*p+1][i]);
                acc0[p] = fma2(hp, w0, acc0[p]);
                acc1[p] = fma2(hp, w1, acc1[p]);
            }
        }
        float bb0 = b1v[tid], bb1 = b1v[256 + tid];
        #pragma unroll
        for (int p = 0; p < 4; p++) {
            float a0, a1, c0, c1;
            unpack2(acc0[p], a0, a1);
            unpack2(acc1[p], c0, c1);
            st[2*p][tid]           = gelu_tanh(a0 + bb0);
            st[2*p][256 + tid]     = gelu_tanh(c0 + bb1);
            st[2*p + 1][tid]       = gelu_tanh(a1 + bb0);
            st[2*p + 1][256 + tid] = gelu_tanh(c1 + bb1);
        }
    }
    __syncthreads();
    {
        int col = tid & 127, half = tid >> 7;       // half 0: queries 0-3, half 1: 4-7
        ull a01 = 0ull, a23 = 0ull;
        #pragma unroll 4
        for (int i = 0; i < 512; i++) {
            ull wv = pack2(W2[i*128 + col]);
            a01 = fma2(packab(st[half*4 + 0][i], st[half*4 + 1][i]), wv, a01);
            a23 = fma2(packab(st[half*4 + 2][i], st[half*4 + 3][i]), wv, a23);
        }
        float v0, v1, v2, v3;
        unpack2(a01, v0, v1);
        unpack2(a23, v2, v3);
        float bb = b2v[col];
        int qb = q0 + half * 4;
        if (qb + 0 < N) g_x[(qb+0)*DM + col] += v0 + bb;
        if (qb + 1 < N) g_x[(qb+1)*DM + col] += v1 + bb;
        if (qb + 2 < N) g_x[(qb+2)*DM + col] += v2 + bb;
        if (qb + 3 < N) g_x[(qb+3)*DM + col] += v3 + bb;
    }
}

__global__ void logits_kernel(const float* __restrict__ fm, const float* __restrict__ qpos,
                              const int* __restrict__ qbo, int n_off,
                              const int* __restrict__ shapes, float* __restrict__ out) {
    int q = blockIdx.x, tid = threadIdx.x;
    int lane = tid & 31, w = tid >> 5;
    __shared__ float sx[128];
    __shared__ int sb;
    if (tid < 128) sx[tid] = g_x[q*DM + tid];
    if (tid == 0) sb = batch_of(q, qbo, n_off);
    __syncthreads();
    int H0 = shapes[0], W0 = shapes[1];
    float p0 = qpos[2*q], p1 = qpos[2*q+1];
    int c0 = (int)floorf(p0), c1 = (int)floorf(p1);
    float4 xv = *(const float4*)&sx[lane * 4];
    int b = sb;
    for (int pp = w; pp < 49; pp += 8) {
        int gi = c0 + pp / 7 - 3;
        int gj = c1 + pp % 7 - 3;
        bool valid = (gi >= 0 && gi < H0 && gj >= 0 && gj < W0);
        int ci = min(max(gi, 0), H0 - 1), cj = min(max(gj, 0), W0 - 1);
        const float* f = fm + ((((size_t)b * 256 + ci) * 256 + cj) * 4 + 0) * 128;
        float4 fv = *(const float4*)(f + lane * 4);
        float d = fv.x*xv.x + fv.y*xv.y + fv.z*xv.z + fv.w*xv.w;
        #pragma unroll
        for (int o = 16; o; o >>= 1) d += __shfl_xor_sync(0xffffffffu, d, o);
        if (lane == 0) out[q*49 + pp] = valid ? d : 0.f;
    }
}

// ---------------- launch ----------------
extern "C" void kernel_launch(void* const* d_in, const int* in_sizes, int n_in,
                              void* d_out, int out_size) {
    const float* queries = (const float*)d_in[0];
    const int*   qbo     = (const int*)  d_in[1];
    const float* qpos    = (const float*)d_in[2];
    const float* fm      = (const float*)d_in[3];
    const int*   shapes  = (const int*)  d_in[4];
    const float* Wq      = (const float*)d_in[5];
    const float* Wk      = (const float*)d_in[6];
    const float* Wv      = (const float*)d_in[7];
    const float* Wo      = (const float*)d_in[8];
    const float* ln1g    = (const float*)d_in[9];
    const float* ln1b    = (const float*)d_in[10];
    const float* ln2g    = (const float*)d_in[11];
    const float* ln2b    = (const float*)d_in[12];
    const float* W1      = (const float*)d_in[13];
    const float* b1      = (const float*)d_in[14];
    const float* W2      = (const float*)d_in[15];
    const float* b2      = (const float*)d_in[16];

    int N     = in_sizes[0] / DM;
    int n_off = in_sizes[1];
    int nl    = in_sizes[5] / (DM * DM);
    int B     = in_sizes[3] / (256 * 256 * 4 * DM);
    int R123  = B * PER_B;
    int R     = R123 + N * 9;
    int gridR = (R + 127) / 128;

    cudaFuncSetAttribute(kvproj_mma_kernel, cudaFuncAttributeMaxDynamicSharedMemorySize, SM_MMA_TOTAL);

    // prep1 section offsets
    int s0 = (N * DM + 255) / 256;
    int s1 = (R + 255) / 256;
    int s2 = (nl * 256 * 128 + 255) / 256;
    int s3 = (4 * 2 * 264 + 255) / 256;
    int s4 = (N + 255) / 256;
    int o1 = s0, o2 = o1 + s1, o3 = o2 + s2, o4 = o3 + s3;
    int gridP1 = o4 + s4;

    int KB = (N * KTOT + 127) / 128;
    int RB = (R * 16 + 127) / 128;
    int gridP2 = N + KB + RB;

    prep1_kernel<<<gridP1, 256>>>(queries, qpos, qbo, n_off, shapes, Wk, Wv,
                                  N, nl, R123, R, o1, o2, o3, o4);
    prep2_kernel<<<gridP2, 128>>>(ln1g, ln1b, Wq, qpos, qbo, n_off, shapes, N, R123, R, KB);
    kvproj_mma_kernel<<<gridR, 256, SM_MMA_TOTAL>>>(fm, 0, R);
    attn_kernel<<<N, 128>>>();                      // my-index 3 -> profiled
    oproj_ln2_kernel<<<N, 128>>>(Wo, ln2g, ln2b);
    ffn_kernel<<<(N + 7) / 8, 256>>>(W1, b1, W2, b2, N);

    for (int li = 1; li < nl; li++) {
        kvproj_mma_kernel<<<gridR, 256, SM_MMA_TOTAL>>>(fm, li, R);
        ln_qproj_kernel<<<N, 128>>>(ln1g + li*DM, ln1b + li*DM, Wq + li*DM*DM);
        attn_kernel<<<N, 128>>>();
        oproj_ln2_kernel<<<N, 128>>>(Wo + li*DM*DM, ln2g + li*DM, ln2b + li*DM);
        ffn_kernel<<<(N + 7) / 8, 256>>>(W1 + li*DM*512, b1 + li*512, W2 + li*512*DM, b2 + li*DM, N);
    }
    logits_kernel<<<N, 256>>>(fm, qpos, qbo, n_off, shapes, (float*)d_out);
}